// round 3
// baseline (speedup 1.0000x reference)
#include <cuda_runtime.h>
#include <math.h>

// GRU: T=2048, B=64, IN=256, H=256, L=3
// Output = [seq (2048*64*256) floats][h_n (3*64*256) floats]
//
// Per layer:
//   Phase A: gemm_gx: g_gx[t*B+b][g] = sum_k A[t*B+b][k]*Wih[g][k] + bih[g]
//   Phase B: gru_scan: persistent 128-CTA kernel, grid software barrier per
//            timestep. CTA c owns hidden units {2c, 2c+1}; its 6 Whh rows
//            live in registers for the whole T loop. h_t is read from the
//            layer's own output buffer (row t-1), so no ping-pong buffers.

#define T_STEPS 2048
#define B_SZ    64
#define H_SZ    256
#define G3      768
#define M_TOT   (T_STEPS * B_SZ)   // 131072

// ---------------- device scratch (no cudaMalloc allowed) -------------------
__device__ float g_gx[(size_t)M_TOT * G3];     // 402 MB input projections
__device__ float g_seq[(size_t)M_TOT * H_SZ];  // 134 MB inter-layer sequence
__device__ unsigned int g_arrive;

__global__ void reset_kernel() { g_arrive = 0u; }

// ---------------- Phase A: gx GEMM  (C[M,768] = A[M,256] @ W[768,256]^T + b)
__global__ __launch_bounds__(256) void gemm_gx(
    const float* __restrict__ A,
    const float* __restrict__ W,
    const float* __restrict__ bias)
{
    __shared__ float As[32 * 132];   // [k][m], pitch 132
    __shared__ float Bs[32 * 64];    // [k][n]

    const int tid = threadIdx.x;
    const int tx  = tid & 15;        // n dim
    const int ty  = tid >> 4;        // m dim
    const int m0  = blockIdx.x * 128;
    const int n0  = blockIdx.y * 64;

    float acc[8][4];
#pragma unroll
    for (int i = 0; i < 8; i++)
#pragma unroll
        for (int j = 0; j < 4; j++) acc[i][j] = 0.0f;

    for (int k0 = 0; k0 < 256; k0 += 32) {
#pragma unroll
        for (int i = 0; i < 4; i++) {             // A tile 128x32
            int f = tid + 256 * i;
            int r = f >> 3, c4 = f & 7;
            float4 v = *(const float4*)(A + (size_t)(m0 + r) * 256 + k0 + c4 * 4);
            As[(c4 * 4 + 0) * 132 + r] = v.x;
            As[(c4 * 4 + 1) * 132 + r] = v.y;
            As[(c4 * 4 + 2) * 132 + r] = v.z;
            As[(c4 * 4 + 3) * 132 + r] = v.w;
        }
#pragma unroll
        for (int i = 0; i < 2; i++) {             // W tile 64x32
            int f = tid + 256 * i;
            int r = f >> 3, c4 = f & 7;
            float4 v = *(const float4*)(W + (size_t)(n0 + r) * 256 + k0 + c4 * 4);
            Bs[(c4 * 4 + 0) * 64 + r] = v.x;
            Bs[(c4 * 4 + 1) * 64 + r] = v.y;
            Bs[(c4 * 4 + 2) * 64 + r] = v.z;
            Bs[(c4 * 4 + 3) * 64 + r] = v.w;
        }
        __syncthreads();

#pragma unroll
        for (int k = 0; k < 32; k++) {
            float a[8], b[4];
            *(float4*)&a[0] = *(const float4*)&As[k * 132 + ty * 8];
            *(float4*)&a[4] = *(const float4*)&As[k * 132 + ty * 8 + 4];
            *(float4*)&b[0] = *(const float4*)&Bs[k * 64 + tx * 4];
#pragma unroll
            for (int i = 0; i < 8; i++)
#pragma unroll
                for (int j = 0; j < 4; j++)
                    acc[i][j] = fmaf(a[i], b[j], acc[i][j]);
        }
        __syncthreads();
    }

    float4 bv = *(const float4*)(bias + n0 + tx * 4);
#pragma unroll
    for (int i = 0; i < 8; i++) {
        float4 o;
        o.x = acc[i][0] + bv.x;
        o.y = acc[i][1] + bv.y;
        o.z = acc[i][2] + bv.z;
        o.w = acc[i][3] + bv.w;
        *(float4*)(g_gx + (size_t)(m0 + ty * 8 + i) * G3 + n0 + tx * 4) = o;
    }
}

// ---------------- gate activations ------------------------------------------
__device__ __forceinline__ float fsigmoid(float x) {
    float e;
    asm("ex2.approx.f32 %0, %1;" : "=f"(e) : "f"(-1.4426950408889634f * x));
    float r;
    asm("rcp.approx.f32 %0, %1;" : "=f"(r) : "f"(1.0f + e));
    return r;
}
__device__ __forceinline__ float ftanh(float x) {
    float y;
    asm("tanh.approx.f32 %0, %1;" : "=f"(y) : "f"(x));
    return y;
}

// ---------------- Phase B: persistent recurrent scan -----------------------
// 128 CTAs x 256 threads. CTA owns units u0=2*blockIdx.x, u0+1 (6 gate rows).
// Thread layout: warp w (0..7), lane l; ks = l&15 (k-slice), bh = l>>4.
// Thread's 4 batches: b0 = (w*2+bh)*4. Thread's k set: {kk*64 + ks*4 + e}.
// Whh slice (6x16 floats) preloaded into registers once.
__global__ __launch_bounds__(256, 1) void gru_scan(
    const float* __restrict__ h0l,   // [64,256] initial h for this layer
    const float* __restrict__ Whh,   // [768,256] this layer
    const float* __restrict__ bhh,   // [768]
    float* __restrict__ seqout,      // [2048,64,256] layer output (also h_t)
    float* __restrict__ hn_out)      // [64,256] final h
{
    const int tid = threadIdx.x;
    const int w   = tid >> 5;
    const int l   = tid & 31;
    const int ks  = l & 15;
    const int bh  = l >> 4;
    const int b0  = (w * 2 + bh) * 4;
    const int u0  = blockIdx.x * 2;

    int rows[6];
    rows[0] = u0;       rows[1] = u0 + 1;
    rows[2] = 256 + u0; rows[3] = 257 + u0;
    rows[4] = 512 + u0; rows[5] = 513 + u0;

    // Preload Whh slice: wgt[r][kk*4+e] <-> k = kk*64 + ks*4 + e
    float wgt[6][16];
#pragma unroll
    for (int r = 0; r < 6; r++) {
#pragma unroll
        for (int kk = 0; kk < 4; kk++) {
            float4 v = *(const float4*)(Whh + (size_t)rows[r] * 256 + kk * 64 + ks * 4);
            wgt[r][kk * 4 + 0] = v.x;
            wgt[r][kk * 4 + 1] = v.y;
            wgt[r][kk * 4 + 2] = v.z;
            wgt[r][kk * 4 + 3] = v.w;
        }
    }
    float bh6[6];
#pragma unroll
    for (int r = 0; r < 6; r++) bh6[r] = bhh[rows[r]];

    const int j = ks;  // lanes j<4 (per 16-lane half) do the combine for batch b0+j

    for (int t = 0; t < T_STEPS; t++) {
        const float* hsrc = (t == 0) ? h0l : (seqout + (size_t)(t - 1) * (B_SZ * H_SZ));

        // Early loads for combine lanes (latency hidden under FMA phase)
        float gxv[6];
        float hold0 = 0.0f, hold1 = 0.0f;
        if (j < 4) {
            const int b = b0 + j;
            const float* gxp = g_gx + ((size_t)t * B_SZ + b) * G3;
#pragma unroll
            for (int r = 0; r < 6; r++) gxv[r] = __ldg(gxp + rows[r]);
            hold0 = __ldcg(hsrc + b * 256 + u0);
            hold1 = __ldcg(hsrc + b * 256 + u0 + 1);
        }

        float acc[6][4];
#pragma unroll
        for (int r = 0; r < 6; r++)
#pragma unroll
            for (int b = 0; b < 4; b++) acc[r][b] = 0.0f;

        // Software-pipelined h loads (coalesced: 16 lanes x float4 contiguous)
        float4 hv[4];
#pragma unroll
        for (int b = 0; b < 4; b++)
            hv[b] = __ldcg((const float4*)(hsrc + (b0 + b) * 256 + ks * 4));

#pragma unroll
        for (int kk = 0; kk < 4; kk++) {
            float4 cur[4];
#pragma unroll
            for (int b = 0; b < 4; b++) cur[b] = hv[b];
            if (kk < 3) {
#pragma unroll
                for (int b = 0; b < 4; b++)
                    hv[b] = __ldcg((const float4*)(hsrc + (b0 + b) * 256 + (kk + 1) * 64 + ks * 4));
            }
#pragma unroll
            for (int r = 0; r < 6; r++) {
#pragma unroll
                for (int b = 0; b < 4; b++) {
                    acc[r][b] = fmaf(wgt[r][kk * 4 + 0], cur[b].x, acc[r][b]);
                    acc[r][b] = fmaf(wgt[r][kk * 4 + 1], cur[b].y, acc[r][b]);
                    acc[r][b] = fmaf(wgt[r][kk * 4 + 2], cur[b].z, acc[r][b]);
                    acc[r][b] = fmaf(wgt[r][kk * 4 + 3], cur[b].w, acc[r][b]);
                }
            }
        }

        // Reduce over the 16 k-slices (butterfly stays within each 16-lane half)
#pragma unroll
        for (int off = 1; off < 16; off <<= 1) {
#pragma unroll
            for (int r = 0; r < 6; r++)
#pragma unroll
                for (int b = 0; b < 4; b++)
                    acc[r][b] += __shfl_xor_sync(0xFFFFFFFFu, acc[r][b], off);
        }

        // Combine gates + write h_t
        if (j < 4) {
            const int b = b0 + j;
            float out0, out1;
            {
                float rr = fsigmoid(gxv[0] + acc[0][j] + bh6[0]);
                float zz = fsigmoid(gxv[2] + acc[2][j] + bh6[2]);
                float nn = ftanh(gxv[4] + rr * (acc[4][j] + bh6[4]));
                out0 = (1.0f - zz) * nn + zz * hold0;
            }
            {
                float rr = fsigmoid(gxv[1] + acc[1][j] + bh6[1]);
                float zz = fsigmoid(gxv[3] + acc[3][j] + bh6[3]);
                float nn = ftanh(gxv[5] + rr * (acc[5][j] + bh6[5]));
                out1 = (1.0f - zz) * nn + zz * hold1;
            }
            float* op = seqout + ((size_t)t * B_SZ + b) * H_SZ + u0;
            op[0] = out0;
            op[1] = out1;
            if (t == T_STEPS - 1) {
                hn_out[b * 256 + u0]     = out0;
                hn_out[b * 256 + u0 + 1] = out1;
            }
        }

        // Grid-wide software barrier (all 128 CTAs are co-resident: 1 CTA/SM)
        __syncthreads();
        if (tid == 0) {
            __threadfence();                      // release our h_t stores
            atomicAdd(&g_arrive, 1u);
            const unsigned int target = (unsigned int)(t + 1) * gridDim.x;
            volatile unsigned int* va = &g_arrive;
            while (*va < target) { }
            __threadfence();                      // acquire others' h_t stores
        }
        __syncthreads();
    }
}

// ---------------- launch -----------------------------------------------------
extern "C" void kernel_launch(void* const* d_in, const int* in_sizes, int n_in,
                              void* d_out, int out_size)
{
    const float* x   = (const float*)d_in[0];   // [2048,64,256]
    const float* h0  = (const float*)d_in[1];   // [3,64,256]
    const float* Wih = (const float*)d_in[2];   // [3,768,256]
    const float* Whh = (const float*)d_in[3];   // [3,768,256]
    const float* bih = (const float*)d_in[4];   // [3,768]
    const float* bhh = (const float*)d_in[5];   // [3,768]

    float* out     = (float*)d_out;
    float* hn_base = out + (size_t)T_STEPS * B_SZ * H_SZ;

    void* gseq_ptr = nullptr;
    cudaGetSymbolAddress(&gseq_ptr, g_seq);
    float* gseq = (float*)gseq_ptr;

    const dim3 ggrid(M_TOT / 128, G3 / 64);     // (1024, 12)
    const size_t WSTRIDE = (size_t)G3 * 256;    // per-layer weight stride
    const size_t HSTRIDE = (size_t)B_SZ * H_SZ; // per-layer h stride

    // ---- layer 0 ----
    gemm_gx<<<ggrid, 256>>>(x, Whh ? Wih : Wih, bih);  // A = x
    reset_kernel<<<1, 1>>>();
    gru_scan<<<128, 256>>>(h0, Whh, bhh, gseq, hn_base);

    // ---- layer 1 ----
    gemm_gx<<<ggrid, 256>>>(gseq, Wih + WSTRIDE, bih + G3);
    reset_kernel<<<1, 1>>>();
    gru_scan<<<128, 256>>>(h0 + HSTRIDE, Whh + WSTRIDE, bhh + G3,
                           gseq, hn_base + HSTRIDE);

    // ---- layer 2 (writes final sequence directly to d_out) ----
    gemm_gx<<<ggrid, 256>>>(gseq, Wih + 2 * WSTRIDE, bih + 2 * G3);
    reset_kernel<<<1, 1>>>();
    gru_scan<<<128, 256>>>(h0 + 2 * HSTRIDE, Whh + 2 * WSTRIDE, bhh + 2 * G3,
                           out, hn_base + 2 * HSTRIDE);
}